// round 14
// baseline (speedup 1.0000x reference)
#include <cuda_runtime.h>
#include <cuda_fp16.h>
#include <cstdint>

typedef unsigned int u32;
typedef unsigned long long u64;

#define NROWS 16384
#define KDIM  2048
#define MDIM  2048
#define EPSF  1e-6f
#define TINYF 1e-15f

// ---- GEMM tiling: 128x128 CTA, 4 warps (2x2, 64x64 each), 2 CTAs/SM ----
#define BM 128
#define BN 128
#define BK 64
#define NIT (KDIM / BK)  // 32
#define ROWB 144
#define T_A (128 * ROWB)
#define T_B (128 * ROWB)
#define SM_A 0
#define SM_B T_A
#define STAGE_BYTES (T_A + T_B)           // 36864
#define NSTAGE 3
#define SMEM_DYN (NSTAGE * STAGE_BYTES)   // 110592 -> 2 CTAs/SM (221KB of 228KB)
#define NTHREADS 128

static __device__ __align__(16) __half g_Ahi[(size_t)NROWS * KDIM];
static __device__ __align__(16) __half g_Bhi[(size_t)MDIM * KDIM];
static __device__ float g_nu2[NROWS];
static __device__ float g_dub[NROWS];
static __device__ float g_alpha[NROWS];
static __device__ float g_gamma[NROWS];
static __device__ float g_nb2;

// ---------------- PTX helpers (sm_80-portable only) ----------------
__device__ __forceinline__ u32 smem_u32(const void* p) {
    u32 a;
    asm("{ .reg .u64 t; cvta.to.shared.u64 t, %1; cvt.u32.u64 %0, t; }"
        : "=r"(a) : "l"(p));
    return a;
}
__device__ __forceinline__ void cp16(u32 dst, const void* src) {
    asm volatile("cp.async.cg.shared.global [%0], [%1], 16;" :: "r"(dst), "l"(src));
}
#define CP_COMMIT()  asm volatile("cp.async.commit_group;" ::: "memory")
#define CP_WAIT1()   asm volatile("cp.async.wait_group 1;" ::: "memory")
#define CP_WAIT0()   asm volatile("cp.async.wait_group 0;" ::: "memory")

__device__ __forceinline__ void ldm4(u32 &r0, u32 &r1, u32 &r2, u32 &r3, u32 addr) {
    asm volatile("ldmatrix.sync.aligned.m8n8.x4.shared.b16 {%0,%1,%2,%3}, [%4];"
                 : "=r"(r0), "=r"(r1), "=r"(r2), "=r"(r3) : "r"(addr));
}
__device__ __forceinline__ void mma_f16(float* c, u32 a0, u32 a1, u32 a2, u32 a3,
                                        u32 b0, u32 b1) {
    asm volatile(
        "mma.sync.aligned.m16n8k16.row.col.f32.f16.f16.f32 "
        "{%0,%1,%2,%3}, {%4,%5,%6,%7}, {%8,%9}, {%0,%1,%2,%3};"
        : "+f"(c[0]), "+f"(c[1]), "+f"(c[2]), "+f"(c[3])
        : "r"(a0), "r"(a1), "r"(a2), "r"(a3), "r"(b0), "r"(b1));
}

// ---------------- Kernel 1: log0 + fp16 round of A ----------------
__global__ void splitA_kernel(const float* __restrict__ x) {
    int row = blockIdx.x, t = threadIdx.x;
    const float4* xr = (const float4*)(x + (size_t)row * KDIM);
    float4 v0 = xr[2 * t], v1 = xr[2 * t + 1];
    float acc = v0.x * v0.x + v0.y * v0.y + v0.z * v0.z + v0.w * v0.w
              + v1.x * v1.x + v1.y * v1.y + v1.z * v1.z + v1.w * v1.w;
    #pragma unroll
    for (int o = 16; o; o >>= 1) acc += __shfl_xor_sync(0xffffffffu, acc, o);
    __shared__ float sred[8];
    __shared__ float s_coef;
    int wid = t >> 5, lid = t & 31;
    if (lid == 0) sred[wid] = acc;
    __syncthreads();
    if (t == 0) {
        float s = 0.f;
        for (int i = 0; i < 8; i++) s += sred[i];
        s = sqrtf(s);
        s_coef = asinhf(s) / fmaxf(s, EPSF);
    }
    __syncthreads();
    float rc = s_coef;
    float in[8] = { v0.x, v0.y, v0.z, v0.w, v1.x, v1.y, v1.z, v1.w };
    __align__(16) __half hi[8];
    #pragma unroll
    for (int i = 0; i < 8; i++) hi[i] = __float2half(rc * in[i]);
    size_t o = (size_t)row * KDIM + (size_t)t * 8;
    *(uint4*)(g_Ahi + o) = *(const uint4*)hi;
}

// ---------------- Kernel 2: fp16 round of W + zero rows + ||b||^2 ----------------
__global__ void splitB_kernel(const float* __restrict__ W, const float* __restrict__ b) {
    int row = blockIdx.x, t = threadIdx.x;
    const float4* wr = (const float4*)(W + (size_t)row * KDIM);
    float4 v0 = wr[2 * t], v1 = wr[2 * t + 1];
    float in[8] = { v0.x, v0.y, v0.z, v0.w, v1.x, v1.y, v1.z, v1.w };
    __align__(16) __half hi[8];
    #pragma unroll
    for (int i = 0; i < 8; i++) hi[i] = __float2half(in[i]);
    size_t o = (size_t)row * KDIM + (size_t)t * 8;
    *(uint4*)(g_Bhi + o) = *(const uint4*)hi;
    int z = row * 8 + (t >> 5);
    if ((t & 31) == 0 && z < NROWS) { g_nu2[z] = 0.f; g_dub[z] = 0.f; }

    if (row == 0) {
        const float4* b4 = (const float4*)b;
        float acc = 0.f;
        for (int j = t; j < MDIM / 4; j += 256) {
            float4 v = b4[j];
            acc += v.x * v.x + v.y * v.y + v.z * v.z + v.w * v.w;
        }
        #pragma unroll
        for (int oo = 16; oo; oo >>= 1) acc += __shfl_xor_sync(0xffffffffu, acc, oo);
        __shared__ float sredb[8];
        if ((t & 31) == 0) sredb[t >> 5] = acc;
        __syncthreads();
        if (t == 0) {
            float s = 0.f;
            for (int i = 0; i < 8; i++) s += sredb[i];
            g_nb2 = s;
        }
    }
}

// ---------------- Kernel 3: mma.sync GEMM + fused row reduction ----------------
__device__ __forceinline__ void load_stage(u32 sbase, int s, int kt, int tid,
                                           size_t arow, size_t brow) {
    u32 base = sbase + (u32)s * STAGE_BYTES;
    const __half* gA = g_Ahi + arow * (size_t)KDIM + kt;
    const __half* gB = g_Bhi + brow * (size_t)KDIM + kt;
    #pragma unroll
    for (int i = 0; i < 8; i++) {   // A: 128 rows x 8 chunks = 1024 cp16
        int idx = tid + i * 128;
        int r = idx >> 3, c = idx & 7;
        cp16(base + SM_A + (u32)r * ROWB + (u32)c * 16,
             gA + (size_t)r * KDIM + c * 8);
    }
    #pragma unroll
    for (int i = 0; i < 8; i++) {   // B: 128 rows x 8 chunks = 1024 cp16
        int idx = tid + i * 128;
        int r = idx >> 3, c = idx & 7;
        cp16(base + SM_B + (u32)r * ROWB + (u32)c * 16,
             gB + (size_t)r * KDIM + c * 8);
    }
}

__global__ void __launch_bounds__(NTHREADS, 2)
gemm_kernel(float* __restrict__ U, const float* __restrict__ b) {
    extern __shared__ __align__(128) char smem[];
    const u32 sbase = smem_u32(smem);
    const int tid = threadIdx.x;
    const int wid = tid >> 5, lane = tid & 31;
    const int wm = wid & 1;          // 2 warp-rows (64 rows each)
    const int wn = wid >> 1;         // 2 warp-cols (64 cols each)
    const size_t arow = (size_t)blockIdx.y * BM;
    const size_t brow = (size_t)blockIdx.x * BN;

    const u32 aRow = (u32)(wm * 64 + (lane & 15)) * ROWB + (u32)(lane >> 4) * 16;
    const u32 bRow = (u32)(wn * 64 + ((lane >> 4) << 3) + (lane & 7)) * ROWB
                   + (u32)((lane >> 3) & 1) * 16;

    float acc[4][8][4];
    #pragma unroll
    for (int i = 0; i < 4; i++)
        #pragma unroll
        for (int j = 0; j < 8; j++)
            #pragma unroll
            for (int q = 0; q < 4; q++) acc[i][j][q] = 0.f;

    load_stage(sbase, 0, 0, tid, arow, brow); CP_COMMIT();
    load_stage(sbase, 1, BK, tid, arow, brow); CP_COMMIT();

    for (int it = 0; it < NIT; ++it) {
        if (it == NIT - 1) { CP_WAIT0(); } else { CP_WAIT1(); }
        __syncthreads();
        if (it + 2 < NIT)
            load_stage(sbase, (it + 2) % NSTAGE, (it + 2) * BK, tid, arow, brow);
        CP_COMMIT();

        const u32 tb = sbase + (u32)(it % NSTAGE) * STAGE_BYTES;
        #pragma unroll
        for (int kk = 0; kk < BK; kk += 16) {
            const u32 kb = (u32)kk * 2;
            u32 bh[8][2];
            #pragma unroll
            for (int p = 0; p < 4; p++) {
                u32 bd = tb + SM_B + bRow + (u32)p * (16 * ROWB) + kb;
                ldm4(bh[2 * p][0], bh[2 * p][1], bh[2 * p + 1][0], bh[2 * p + 1][1], bd);
            }
            #pragma unroll
            for (int mt = 0; mt < 4; mt++) {
                u32 ah[4];
                u32 ad = tb + SM_A + aRow + (u32)mt * (16 * ROWB) + kb;
                ldm4(ah[0], ah[1], ah[2], ah[3], ad);
                #pragma unroll
                for (int nt = 0; nt < 8; nt++)
                    mma_f16(acc[mt][nt], ah[0], ah[1], ah[2], ah[3],
                            bh[nt][0], bh[nt][1]);
            }
        }
    }

    // ---- writeout + fused per-row reduction ----
    const int qr = lane >> 2, qc = lane & 3;
    float bv0[8], bv1[8];
    #pragma unroll
    for (int nt = 0; nt < 8; nt++) {
        float2 bb = *(const float2*)(b + brow + (size_t)(wn * 64 + nt * 8 + qc * 2));
        bv0[nt] = bb.x; bv1[nt] = bb.y;
    }
    #pragma unroll
    for (int mt = 0; mt < 4; mt++) {
        size_t r0 = arow + (size_t)(wm * 64 + mt * 16 + qr);
        float su0 = 0.f, sd0 = 0.f, su1 = 0.f, sd1 = 0.f;
        #pragma unroll
        for (int nt = 0; nt < 8; nt++) {
            float c0 = acc[mt][nt][0], c1 = acc[mt][nt][1];
            float c2 = acc[mt][nt][2], c3 = acc[mt][nt][3];
            su0 += c0 * c0 + c1 * c1;
            sd0 += c0 * bv0[nt] + c1 * bv1[nt];
            su1 += c2 * c2 + c3 * c3;
            sd1 += c2 * bv0[nt] + c3 * bv1[nt];
            float* p = U + r0 * MDIM + brow + (size_t)(wn * 64 + nt * 8 + qc * 2);
            *(float2*)p = make_float2(c0, c1);
            *(float2*)(p + 8 * MDIM) = make_float2(c2, c3);
        }
        #pragma unroll
        for (int o = 1; o <= 2; o <<= 1) {
            su0 += __shfl_xor_sync(0xffffffffu, su0, o);
            sd0 += __shfl_xor_sync(0xffffffffu, sd0, o);
            su1 += __shfl_xor_sync(0xffffffffu, su1, o);
            sd1 += __shfl_xor_sync(0xffffffffu, sd1, o);
        }
        if (qc == 0) {
            atomicAdd(&g_nu2[r0], su0);
            atomicAdd(&g_dub[r0], sd0);
            atomicAdd(&g_nu2[r0 + 8], su1);
            atomicAdd(&g_dub[r0 + 8], sd1);
        }
    }
}

// ---------------- Kernel 3b: per-row coefficients ----------------
__global__ void coef_kernel() {
    int row = blockIdx.x * 256 + threadIdx.x;
    if (row >= NROWS) return;
    const float nu2 = g_nu2[row], dub = g_dub[row], nb2 = g_nb2;

    float t     = sqrtf(nu2);
    float r     = fmaxf(t, EPSF);
    float scale = fminf(20.f / r, 1.f);
    float ru    = scale * t;
    float coefe = sinhf(ru) / fmaxf(ru, EPSF);
    float cy    = coefe * scale;
    float ny2   = cy * cy * nu2;
    float dyb   = cy * dub;
    float bx    = 1.f / fmaxf(sqrtf(1.f + ny2), TINYF);
    float kk    = bx / (1.f + bx);
    float dxv   = dyb * (1.f + kk * ny2);
    float nbt2  = nb2 + 2.f * kk * dyb * dyb + kk * kk * dyb * dyb * ny2;
    float gpvv  = fmaxf(nbt2 - dxv * dxv / (1.f + ny2), TINYF);
    float rg    = sqrtf(gpvv);
    float opb   = 1.f + bx;
    float mopb  = fmaxf(opb, TINYF);
    float c2    = -(bx * bx * bx) / (mopb * mopb);
    float lam   = opb / fmaxf(bx, TINYF);
    float z     = fminf(rg, 20.f);
    float sc    = (fabsf(z) < EPSF) ? (1.f + z * z / 6.f)
                                    : (sinhf(z) / fmaxf(z, EPSF));
    float L     = lam * sc;
    float wb    = L * kk;
    float wy    = L * (kk * kk * dyb + c2 * dxv);
    float nw2   = wb * wb * nb2 + 2.f * wb * wy * dyb + wy * wy * ny2;
    float dyw   = wb * dyb + wy * ny2;
    float bw    = 1.f / fmaxf(sqrtf(1.f + nw2), TINYF);
    float coefg = kk * dyw + (1.f - bw) / bw;
    g_alpha[row] = (1.f + coefg + wy) * cy;
    g_gamma[row] = wb;
}

// ---------------- Kernel 4: pure streaming epilogue ----------------
__global__ void epilogue_kernel(float* __restrict__ U, const float* __restrict__ b) {
    int row = blockIdx.x;
    const float alpha = g_alpha[row], gamma = g_gamma[row];
    float4* u4 = (float4*)(U + (size_t)row * MDIM);
    const float4* b4 = (const float4*)b;
    #pragma unroll
    for (int q = 0; q < 2; q++) {
        int j = threadIdx.x + q * 256;
        float4 uv = u4[j], bv = b4[j];
        float4 ov;
        ov.x = alpha * uv.x + gamma * bv.x;
        ov.y = alpha * uv.y + gamma * bv.y;
        ov.z = alpha * uv.z + gamma * bv.z;
        ov.w = alpha * uv.w + gamma * bv.w;
        u4[j] = ov;
    }
}

// ---------------- Launch ----------------
extern "C" void kernel_launch(void* const* d_in, const int* in_sizes, int n_in,
                              void* d_out, int out_size) {
    const float* x = (const float*)d_in[0];   // [16384, 2048]
    const float* W = (const float*)d_in[1];   // [2048, 2048]
    const float* b = (const float*)d_in[2];   // [2048]
    float* out = (float*)d_out;               // [16384, 2048]

    cudaFuncSetAttribute(gemm_kernel, cudaFuncAttributeMaxDynamicSharedMemorySize, SMEM_DYN);

    splitB_kernel<<<MDIM, 256>>>(W, b);
    splitA_kernel<<<NROWS, 256>>>(x);

    dim3 grid(MDIM / BN, NROWS / BM);      // (16, 128), 2048 CTAs, 2/SM
    gemm_kernel<<<grid, NTHREADS, SMEM_DYN>>>(out, b);

    coef_kernel<<<NROWS / 256, 256>>>();
    epilogue_kernel<<<NROWS, 256>>>(out, b);
}

// round 16
// speedup vs baseline: 1.0545x; 1.0545x over previous
#include <cuda_runtime.h>
#include <cuda_fp16.h>
#include <cstdint>

typedef unsigned int u32;
typedef unsigned long long u64;

#define NROWS 16384
#define KDIM  2048
#define MDIM  2048
#define EPSF  1e-6f
#define TINYF 1e-15f

// ---- GEMM tiling: 128x128 CTA, 8 warps (2x4, 64x32 each), 2 CTAs/SM (R12) ----
#define BM 128
#define BN 128
#define BK 64
#define NIT (KDIM / BK)  // 32
#define ROWB 144
#define T_A (128 * ROWB)
#define T_B (128 * ROWB)
#define SM_A 0
#define SM_B T_A
#define STAGE_BYTES (T_A + T_B)           // 36864
#define NSTAGE 3
#define SMEM_DYN (NSTAGE * STAGE_BYTES)   // 110592 -> 2 CTAs/SM
#define NTHREADS 256

static __device__ __align__(16) __half g_Ahi[(size_t)NROWS * KDIM];
static __device__ __align__(16) __half g_Bhi[(size_t)MDIM * KDIM];
static __device__ float g_nu2[NROWS];
static __device__ float g_dub[NROWS];
static __device__ float g_alpha[NROWS];
static __device__ float g_gamma[NROWS];
static __device__ float g_nb2;

// ---------------- PTX helpers (sm_80-portable only) ----------------
__device__ __forceinline__ u32 smem_u32(const void* p) {
    u32 a;
    asm("{ .reg .u64 t; cvta.to.shared.u64 t, %1; cvt.u32.u64 %0, t; }"
        : "=r"(a) : "l"(p));
    return a;
}
__device__ __forceinline__ void cp16(u32 dst, const void* src) {
    asm volatile("cp.async.cg.shared.global [%0], [%1], 16;" :: "r"(dst), "l"(src));
}
#define CP_COMMIT()  asm volatile("cp.async.commit_group;" ::: "memory")
#define CP_WAIT1()   asm volatile("cp.async.wait_group 1;" ::: "memory")
#define CP_WAIT0()   asm volatile("cp.async.wait_group 0;" ::: "memory")

__device__ __forceinline__ void ldm4(u32 &r0, u32 &r1, u32 &r2, u32 &r3, u32 addr) {
    asm volatile("ldmatrix.sync.aligned.m8n8.x4.shared.b16 {%0,%1,%2,%3}, [%4];"
                 : "=r"(r0), "=r"(r1), "=r"(r2), "=r"(r3) : "r"(addr));
}
__device__ __forceinline__ void mma_f16(float* c, u32 a0, u32 a1, u32 a2, u32 a3,
                                        u32 b0, u32 b1) {
    asm volatile(
        "mma.sync.aligned.m16n8k16.row.col.f32.f16.f16.f32 "
        "{%0,%1,%2,%3}, {%4,%5,%6,%7}, {%8,%9}, {%0,%1,%2,%3};"
        : "+f"(c[0]), "+f"(c[1]), "+f"(c[2]), "+f"(c[3])
        : "r"(a0), "r"(a1), "r"(a2), "r"(a3), "r"(b0), "r"(b1));
}

// ---------------- Kernel 1: merged prep ----------------
// blocks [0, MDIM):       fp16 round of W row + zero g_nu2/g_dub (+ block 0: ||b||^2)
// blocks [MDIM, +NROWS):  log0 coef + fp16 round of x row
__global__ void prep_kernel(const float* __restrict__ x, const float* __restrict__ W,
                            const float* __restrict__ b) {
    int blk = blockIdx.x, t = threadIdx.x;
    if (blk < MDIM) {
        int row = blk;
        const float4* wr = (const float4*)(W + (size_t)row * KDIM);
        float4 v0 = wr[2 * t], v1 = wr[2 * t + 1];
        float in[8] = { v0.x, v0.y, v0.z, v0.w, v1.x, v1.y, v1.z, v1.w };
        __align__(16) __half hi[8];
        #pragma unroll
        for (int i = 0; i < 8; i++) hi[i] = __float2half(in[i]);
        size_t o = (size_t)row * KDIM + (size_t)t * 8;
        *(uint4*)(g_Bhi + o) = *(const uint4*)hi;
        int z = row * 8 + (t >> 5);
        if ((t & 31) == 0 && z < NROWS) { g_nu2[z] = 0.f; g_dub[z] = 0.f; }

        if (row == 0) {
            const float4* b4 = (const float4*)b;
            float acc = 0.f;
            for (int j = t; j < MDIM / 4; j += 256) {
                float4 v = b4[j];
                acc += v.x * v.x + v.y * v.y + v.z * v.z + v.w * v.w;
            }
            #pragma unroll
            for (int oo = 16; oo; oo >>= 1) acc += __shfl_xor_sync(0xffffffffu, acc, oo);
            __shared__ float sredb[8];
            if ((t & 31) == 0) sredb[t >> 5] = acc;
            __syncthreads();
            if (t == 0) {
                float s = 0.f;
                for (int i = 0; i < 8; i++) s += sredb[i];
                g_nb2 = s;
            }
        }
    } else {
        int row = blk - MDIM;
        const float4* xr = (const float4*)(x + (size_t)row * KDIM);
        float4 v0 = xr[2 * t], v1 = xr[2 * t + 1];
        float acc = v0.x * v0.x + v0.y * v0.y + v0.z * v0.z + v0.w * v0.w
                  + v1.x * v1.x + v1.y * v1.y + v1.z * v1.z + v1.w * v1.w;
        #pragma unroll
        for (int o = 16; o; o >>= 1) acc += __shfl_xor_sync(0xffffffffu, acc, o);
        __shared__ float sred[8];
        __shared__ float s_coef;
        int wid = t >> 5, lid = t & 31;
        if (lid == 0) sred[wid] = acc;
        __syncthreads();
        if (t == 0) {
            float s = 0.f;
            for (int i = 0; i < 8; i++) s += sred[i];
            s = sqrtf(s);
            s_coef = asinhf(s) / fmaxf(s, EPSF);
        }
        __syncthreads();
        float rc = s_coef;
        float in[8] = { v0.x, v0.y, v0.z, v0.w, v1.x, v1.y, v1.z, v1.w };
        __align__(16) __half hi[8];
        #pragma unroll
        for (int i = 0; i < 8; i++) hi[i] = __float2half(rc * in[i]);
        size_t o = (size_t)row * KDIM + (size_t)t * 8;
        *(uint4*)(g_Ahi + o) = *(const uint4*)hi;
    }
}

// ---------------- Kernel 2: mma.sync GEMM + fused row reduction (R12, locked) ----------------
__device__ __forceinline__ void load_stage(u32 sbase, int s, int kt, int tid,
                                           size_t arow, size_t brow) {
    u32 base = sbase + (u32)s * STAGE_BYTES;
    const __half* gA = g_Ahi + arow * (size_t)KDIM + kt;
    const __half* gB = g_Bhi + brow * (size_t)KDIM + kt;
    #pragma unroll
    for (int i = 0; i < 4; i++) {
        int idx = tid + i * 256;
        int r = idx >> 3, c = idx & 7;
        cp16(base + SM_A + (u32)r * ROWB + (u32)c * 16,
             gA + (size_t)r * KDIM + c * 8);
    }
    #pragma unroll
    for (int i = 0; i < 4; i++) {
        int idx = tid + i * 256;
        int r = idx >> 3, c = idx & 7;
        cp16(base + SM_B + (u32)r * ROWB + (u32)c * 16,
             gB + (size_t)r * KDIM + c * 8);
    }
}

__global__ void __launch_bounds__(NTHREADS, 2)
gemm_kernel(float* __restrict__ U, const float* __restrict__ b) {
    extern __shared__ __align__(128) char smem[];
    const u32 sbase = smem_u32(smem);
    const int tid = threadIdx.x;
    const int wid = tid >> 5, lane = tid & 31;
    const int wm = wid & 1;
    const int wn = wid >> 1;
    const size_t arow = (size_t)blockIdx.y * BM;
    const size_t brow = (size_t)blockIdx.x * BN;

    const u32 aRow = (u32)(wm * 64 + (lane & 15)) * ROWB + (u32)(lane >> 4) * 16;
    const u32 bRow = (u32)(wn * 32 + ((lane >> 4) << 3) + (lane & 7)) * ROWB
                   + (u32)((lane >> 3) & 1) * 16;

    float acc[4][4][4];
    #pragma unroll
    for (int i = 0; i < 4; i++)
        #pragma unroll
        for (int j = 0; j < 4; j++)
            #pragma unroll
            for (int q = 0; q < 4; q++) acc[i][j][q] = 0.f;

    load_stage(sbase, 0, 0, tid, arow, brow); CP_COMMIT();
    load_stage(sbase, 1, BK, tid, arow, brow); CP_COMMIT();

    for (int it = 0; it < NIT; ++it) {
        if (it == NIT - 1) { CP_WAIT0(); } else { CP_WAIT1(); }
        __syncthreads();
        if (it + 2 < NIT)
            load_stage(sbase, (it + 2) % NSTAGE, (it + 2) * BK, tid, arow, brow);
        CP_COMMIT();

        const u32 tb = sbase + (u32)(it % NSTAGE) * STAGE_BYTES;
        #pragma unroll
        for (int kk = 0; kk < BK; kk += 16) {
            const u32 kb = (u32)kk * 2;
            u32 bh[4][2];
            #pragma unroll
            for (int p = 0; p < 2; p++) {
                u32 bd = tb + SM_B + bRow + (u32)p * (16 * ROWB) + kb;
                ldm4(bh[2 * p][0], bh[2 * p][1], bh[2 * p + 1][0], bh[2 * p + 1][1], bd);
            }
            #pragma unroll
            for (int mt = 0; mt < 4; mt++) {
                u32 ah[4];
                u32 ad = tb + SM_A + aRow + (u32)mt * (16 * ROWB) + kb;
                ldm4(ah[0], ah[1], ah[2], ah[3], ad);
                #pragma unroll
                for (int nt = 0; nt < 4; nt++)
                    mma_f16(acc[mt][nt], ah[0], ah[1], ah[2], ah[3],
                            bh[nt][0], bh[nt][1]);
            }
        }
    }

    const int qr = lane >> 2, qc = lane & 3;
    float bv0[4], bv1[4];
    #pragma unroll
    for (int nt = 0; nt < 4; nt++) {
        float2 bb = *(const float2*)(b + brow + (size_t)(wn * 32 + nt * 8 + qc * 2));
        bv0[nt] = bb.x; bv1[nt] = bb.y;
    }
    #pragma unroll
    for (int mt = 0; mt < 4; mt++) {
        size_t r0 = arow + (size_t)(wm * 64 + mt * 16 + qr);
        float su0 = 0.f, sd0 = 0.f, su1 = 0.f, sd1 = 0.f;
        #pragma unroll
        for (int nt = 0; nt < 4; nt++) {
            float c0 = acc[mt][nt][0], c1 = acc[mt][nt][1];
            float c2 = acc[mt][nt][2], c3 = acc[mt][nt][3];
            su0 += c0 * c0 + c1 * c1;
            sd0 += c0 * bv0[nt] + c1 * bv1[nt];
            su1 += c2 * c2 + c3 * c3;
            sd1 += c2 * bv0[nt] + c3 * bv1[nt];
            float* p = U + r0 * MDIM + brow + (size_t)(wn * 32 + nt * 8 + qc * 2);
            *(float2*)p = make_float2(c0, c1);
            *(float2*)(p + 8 * MDIM) = make_float2(c2, c3);
        }
        #pragma unroll
        for (int o = 1; o <= 2; o <<= 1) {
            su0 += __shfl_xor_sync(0xffffffffu, su0, o);
            sd0 += __shfl_xor_sync(0xffffffffu, sd0, o);
            su1 += __shfl_xor_sync(0xffffffffu, su1, o);
            sd1 += __shfl_xor_sync(0xffffffffu, sd1, o);
        }
        if (qc == 0) {
            atomicAdd(&g_nu2[r0], su0);
            atomicAdd(&g_dub[r0], sd0);
            atomicAdd(&g_nu2[r0 + 8], su1);
            atomicAdd(&g_dub[r0 + 8], sd1);
        }
    }
}

// ---------------- Kernel 3: per-row coefficients ----------------
__global__ void coef_kernel() {
    int row = blockIdx.x * 256 + threadIdx.x;
    if (row >= NROWS) return;
    const float nu2 = g_nu2[row], dub = g_dub[row], nb2 = g_nb2;

    float t     = sqrtf(nu2);
    float r     = fmaxf(t, EPSF);
    float scale = fminf(20.f / r, 1.f);
    float ru    = scale * t;
    float coefe = sinhf(ru) / fmaxf(ru, EPSF);
    float cy    = coefe * scale;
    float ny2   = cy * cy * nu2;
    float dyb   = cy * dub;
    float bx    = 1.f / fmaxf(sqrtf(1.f + ny2), TINYF);
    float kk    = bx / (1.f + bx);
    float dxv   = dyb * (1.f + kk * ny2);
    float nbt2  = nb2 + 2.f * kk * dyb * dyb + kk * kk * dyb * dyb * ny2;
    float gpvv  = fmaxf(nbt2 - dxv * dxv / (1.f + ny2), TINYF);
    float rg    = sqrtf(gpvv);
    float opb   = 1.f + bx;
    float mopb  = fmaxf(opb, TINYF);
    float c2    = -(bx * bx * bx) / (mopb * mopb);
    float lam   = opb / fmaxf(bx, TINYF);
    float z     = fminf(rg, 20.f);
    float sc    = (fabsf(z) < EPSF) ? (1.f + z * z / 6.f)
                                    : (sinhf(z) / fmaxf(z, EPSF));
    float L     = lam * sc;
    float wb    = L * kk;
    float wy    = L * (kk * kk * dyb + c2 * dxv);
    float nw2   = wb * wb * nb2 + 2.f * wb * wy * dyb + wy * wy * ny2;
    float dyw   = wb * dyb + wy * ny2;
    float bw    = 1.f / fmaxf(sqrtf(1.f + nw2), TINYF);
    float coefg = kk * dyw + (1.f - bw) / bw;
    g_alpha[row] = (1.f + coefg + wy) * cy;
    g_gamma[row] = wb;
}

// ---------------- Kernel 4: pure streaming epilogue ----------------
__global__ void epilogue_kernel(float* __restrict__ U, const float* __restrict__ b) {
    int row = blockIdx.x;
    const float alpha = g_alpha[row], gamma = g_gamma[row];
    float4* u4 = (float4*)(U + (size_t)row * MDIM);
    const float4* b4 = (const float4*)b;
    #pragma unroll
    for (int q = 0; q < 2; q++) {
        int j = threadIdx.x + q * 256;
        float4 uv = u4[j], bv = b4[j];
        float4 ov;
        ov.x = alpha * uv.x + gamma * bv.x;
        ov.y = alpha * uv.y + gamma * bv.y;
        ov.z = alpha * uv.z + gamma * bv.z;
        ov.w = alpha * uv.w + gamma * bv.w;
        u4[j] = ov;
    }
}

// ---------------- Launch ----------------
extern "C" void kernel_launch(void* const* d_in, const int* in_sizes, int n_in,
                              void* d_out, int out_size) {
    const float* x = (const float*)d_in[0];   // [16384, 2048]
    const float* W = (const float*)d_in[1];   // [2048, 2048]
    const float* b = (const float*)d_in[2];   // [2048]
    float* out = (float*)d_out;               // [16384, 2048]

    cudaFuncSetAttribute(gemm_kernel, cudaFuncAttributeMaxDynamicSharedMemorySize, SMEM_DYN);

    prep_kernel<<<MDIM + NROWS, 256>>>(x, W, b);

    dim3 grid(MDIM / BN, NROWS / BM);      // (16, 128), 2048 CTAs, 2/SM
    gemm_kernel<<<grid, NTHREADS, SMEM_DYN>>>(out, b);

    coef_kernel<<<NROWS / 256, 256>>>();
    epilogue_kernel<<<NROWS, 256>>>(out, b);
}

// round 17
// speedup vs baseline: 1.0654x; 1.0103x over previous
#include <cuda_runtime.h>
#include <cuda_fp16.h>
#include <cstdint>

typedef unsigned int u32;
typedef unsigned long long u64;

#define NROWS 16384
#define KDIM  2048
#define MDIM  2048
#define EPSF  1e-6f
#define TINYF 1e-15f

// ---- GEMM tiling: 128x128 CTA, 8 warps (2x4, 64x32 each), 2 CTAs/SM (locked) ----
#define BM 128
#define BN 128
#define BK 64
#define NIT (KDIM / BK)  // 32
#define ROWB 144
#define T_A (128 * ROWB)
#define T_B (128 * ROWB)
#define SM_A 0
#define SM_B T_A
#define STAGE_BYTES (T_A + T_B)           // 36864
#define NSTAGE 3
#define SMEM_DYN (NSTAGE * STAGE_BYTES)   // 110592 -> 2 CTAs/SM
#define NTHREADS 256

static __device__ __align__(16) __half g_Ahi[(size_t)NROWS * KDIM];
static __device__ __align__(16) __half g_Bhi[(size_t)MDIM * KDIM];
static __device__ __align__(16) __half g_Uh[(size_t)NROWS * MDIM];   // fp16 intermediate
static __device__ float g_nu2[NROWS];
static __device__ float g_dub[NROWS];
static __device__ float g_alpha[NROWS];
static __device__ float g_gamma[NROWS];
static __device__ float g_nb2;

// ---------------- PTX helpers (sm_80-portable only) ----------------
__device__ __forceinline__ u32 smem_u32(const void* p) {
    u32 a;
    asm("{ .reg .u64 t; cvta.to.shared.u64 t, %1; cvt.u32.u64 %0, t; }"
        : "=r"(a) : "l"(p));
    return a;
}
__device__ __forceinline__ void cp16(u32 dst, const void* src) {
    asm volatile("cp.async.cg.shared.global [%0], [%1], 16;" :: "r"(dst), "l"(src));
}
#define CP_COMMIT()  asm volatile("cp.async.commit_group;" ::: "memory")
#define CP_WAIT1()   asm volatile("cp.async.wait_group 1;" ::: "memory")
#define CP_WAIT0()   asm volatile("cp.async.wait_group 0;" ::: "memory")

__device__ __forceinline__ void ldm4(u32 &r0, u32 &r1, u32 &r2, u32 &r3, u32 addr) {
    asm volatile("ldmatrix.sync.aligned.m8n8.x4.shared.b16 {%0,%1,%2,%3}, [%4];"
                 : "=r"(r0), "=r"(r1), "=r"(r2), "=r"(r3) : "r"(addr));
}
__device__ __forceinline__ void mma_f16(float* c, u32 a0, u32 a1, u32 a2, u32 a3,
                                        u32 b0, u32 b1) {
    asm volatile(
        "mma.sync.aligned.m16n8k16.row.col.f32.f16.f16.f32 "
        "{%0,%1,%2,%3}, {%4,%5,%6,%7}, {%8,%9}, {%0,%1,%2,%3};"
        : "+f"(c[0]), "+f"(c[1]), "+f"(c[2]), "+f"(c[3])
        : "r"(a0), "r"(a1), "r"(a2), "r"(a3), "r"(b0), "r"(b1));
}

// ---------------- Kernel 1: merged prep ----------------
__global__ void prep_kernel(const float* __restrict__ x, const float* __restrict__ W,
                            const float* __restrict__ b) {
    int blk = blockIdx.x, t = threadIdx.x;
    if (blk < MDIM) {
        int row = blk;
        const float4* wr = (const float4*)(W + (size_t)row * KDIM);
        float4 v0 = wr[2 * t], v1 = wr[2 * t + 1];
        float in[8] = { v0.x, v0.y, v0.z, v0.w, v1.x, v1.y, v1.z, v1.w };
        __align__(16) __half hi[8];
        #pragma unroll
        for (int i = 0; i < 8; i++) hi[i] = __float2half(in[i]);
        size_t o = (size_t)row * KDIM + (size_t)t * 8;
        *(uint4*)(g_Bhi + o) = *(const uint4*)hi;
        int z = row * 8 + (t >> 5);
        if ((t & 31) == 0 && z < NROWS) { g_nu2[z] = 0.f; g_dub[z] = 0.f; }

        if (row == 0) {
            const float4* b4 = (const float4*)b;
            float acc = 0.f;
            for (int j = t; j < MDIM / 4; j += 256) {
                float4 v = b4[j];
                acc += v.x * v.x + v.y * v.y + v.z * v.z + v.w * v.w;
            }
            #pragma unroll
            for (int oo = 16; oo; oo >>= 1) acc += __shfl_xor_sync(0xffffffffu, acc, oo);
            __shared__ float sredb[8];
            if ((t & 31) == 0) sredb[t >> 5] = acc;
            __syncthreads();
            if (t == 0) {
                float s = 0.f;
                for (int i = 0; i < 8; i++) s += sredb[i];
                g_nb2 = s;
            }
        }
    } else {
        int row = blk - MDIM;
        const float4* xr = (const float4*)(x + (size_t)row * KDIM);
        float4 v0 = xr[2 * t], v1 = xr[2 * t + 1];
        float acc = v0.x * v0.x + v0.y * v0.y + v0.z * v0.z + v0.w * v0.w
                  + v1.x * v1.x + v1.y * v1.y + v1.z * v1.z + v1.w * v1.w;
        #pragma unroll
        for (int o = 16; o; o >>= 1) acc += __shfl_xor_sync(0xffffffffu, acc, o);
        __shared__ float sred[8];
        __shared__ float s_coef;
        int wid = t >> 5, lid = t & 31;
        if (lid == 0) sred[wid] = acc;
        __syncthreads();
        if (t == 0) {
            float s = 0.f;
            for (int i = 0; i < 8; i++) s += sred[i];
            s = sqrtf(s);
            s_coef = asinhf(s) / fmaxf(s, EPSF);
        }
        __syncthreads();
        float rc = s_coef;
        float in[8] = { v0.x, v0.y, v0.z, v0.w, v1.x, v1.y, v1.z, v1.w };
        __align__(16) __half hi[8];
        #pragma unroll
        for (int i = 0; i < 8; i++) hi[i] = __float2half(rc * in[i]);
        size_t o = (size_t)row * KDIM + (size_t)t * 8;
        *(uint4*)(g_Ahi + o) = *(const uint4*)hi;
    }
}

// ---------------- Kernel 2: mma.sync GEMM -> fp16 U + fused row reduction ----------------
__device__ __forceinline__ void load_stage(u32 sbase, int s, int kt, int tid,
                                           size_t arow, size_t brow) {
    u32 base = sbase + (u32)s * STAGE_BYTES;
    const __half* gA = g_Ahi + arow * (size_t)KDIM + kt;
    const __half* gB = g_Bhi + brow * (size_t)KDIM + kt;
    #pragma unroll
    for (int i = 0; i < 4; i++) {
        int idx = tid + i * 256;
        int r = idx >> 3, c = idx & 7;
        cp16(base + SM_A + (u32)r * ROWB + (u32)c * 16,
             gA + (size_t)r * KDIM + c * 8);
    }
    #pragma unroll
    for (int i = 0; i < 4; i++) {
        int idx = tid + i * 256;
        int r = idx >> 3, c = idx & 7;
        cp16(base + SM_B + (u32)r * ROWB + (u32)c * 16,
             gB + (size_t)r * KDIM + c * 8);
    }
}

__global__ void __launch_bounds__(NTHREADS, 2)
gemm_kernel(const float* __restrict__ b) {
    extern __shared__ __align__(128) char smem[];
    const u32 sbase = smem_u32(smem);
    const int tid = threadIdx.x;
    const int wid = tid >> 5, lane = tid & 31;
    const int wm = wid & 1;
    const int wn = wid >> 1;
    const size_t arow = (size_t)blockIdx.y * BM;
    const size_t brow = (size_t)blockIdx.x * BN;

    const u32 aRow = (u32)(wm * 64 + (lane & 15)) * ROWB + (u32)(lane >> 4) * 16;
    const u32 bRow = (u32)(wn * 32 + ((lane >> 4) << 3) + (lane & 7)) * ROWB
                   + (u32)((lane >> 3) & 1) * 16;

    float acc[4][4][4];
    #pragma unroll
    for (int i = 0; i < 4; i++)
        #pragma unroll
        for (int j = 0; j < 4; j++)
            #pragma unroll
            for (int q = 0; q < 4; q++) acc[i][j][q] = 0.f;

    load_stage(sbase, 0, 0, tid, arow, brow); CP_COMMIT();
    load_stage(sbase, 1, BK, tid, arow, brow); CP_COMMIT();

    for (int it = 0; it < NIT; ++it) {
        if (it == NIT - 1) { CP_WAIT0(); } else { CP_WAIT1(); }
        __syncthreads();
        if (it + 2 < NIT)
            load_stage(sbase, (it + 2) % NSTAGE, (it + 2) * BK, tid, arow, brow);
        CP_COMMIT();

        const u32 tb = sbase + (u32)(it % NSTAGE) * STAGE_BYTES;
        #pragma unroll
        for (int kk = 0; kk < BK; kk += 16) {
            const u32 kb = (u32)kk * 2;
            u32 bh[4][2];
            #pragma unroll
            for (int p = 0; p < 2; p++) {
                u32 bd = tb + SM_B + bRow + (u32)p * (16 * ROWB) + kb;
                ldm4(bh[2 * p][0], bh[2 * p][1], bh[2 * p + 1][0], bh[2 * p + 1][1], bd);
            }
            #pragma unroll
            for (int mt = 0; mt < 4; mt++) {
                u32 ah[4];
                u32 ad = tb + SM_A + aRow + (u32)mt * (16 * ROWB) + kb;
                ldm4(ah[0], ah[1], ah[2], ah[3], ad);
                #pragma unroll
                for (int nt = 0; nt < 4; nt++)
                    mma_f16(acc[mt][nt], ah[0], ah[1], ah[2], ah[3],
                            bh[nt][0], bh[nt][1]);
            }
        }
    }

    // ---- writeout (fp16) + fused per-row reduction (fp32-exact sums) ----
    const int qr = lane >> 2, qc = lane & 3;
    float bv0[4], bv1[4];
    #pragma unroll
    for (int nt = 0; nt < 4; nt++) {
        float2 bb = *(const float2*)(b + brow + (size_t)(wn * 32 + nt * 8 + qc * 2));
        bv0[nt] = bb.x; bv1[nt] = bb.y;
    }
    #pragma unroll
    for (int mt = 0; mt < 4; mt++) {
        size_t r0 = arow + (size_t)(wm * 64 + mt * 16 + qr);
        float su0 = 0.f, sd0 = 0.f, su1 = 0.f, sd1 = 0.f;
        #pragma unroll
        for (int nt = 0; nt < 4; nt++) {
            float c0 = acc[mt][nt][0], c1 = acc[mt][nt][1];
            float c2 = acc[mt][nt][2], c3 = acc[mt][nt][3];
            su0 += c0 * c0 + c1 * c1;
            sd0 += c0 * bv0[nt] + c1 * bv1[nt];
            su1 += c2 * c2 + c3 * c3;
            sd1 += c2 * bv0[nt] + c3 * bv1[nt];
            __half* p = g_Uh + r0 * MDIM + brow + (size_t)(wn * 32 + nt * 8 + qc * 2);
            *(__half2*)p = __floats2half2_rn(c0, c1);
            *(__half2*)(p + 8 * MDIM) = __floats2half2_rn(c2, c3);
        }
        #pragma unroll
        for (int o = 1; o <= 2; o <<= 1) {
            su0 += __shfl_xor_sync(0xffffffffu, su0, o);
            sd0 += __shfl_xor_sync(0xffffffffu, sd0, o);
            su1 += __shfl_xor_sync(0xffffffffu, su1, o);
            sd1 += __shfl_xor_sync(0xffffffffu, sd1, o);
        }
        if (qc == 0) {
            atomicAdd(&g_nu2[r0], su0);
            atomicAdd(&g_dub[r0], sd0);
            atomicAdd(&g_nu2[r0 + 8], su1);
            atomicAdd(&g_dub[r0 + 8], sd1);
        }
    }
}

// ---------------- Kernel 3: per-row coefficients ----------------
__global__ void coef_kernel() {
    int row = blockIdx.x * 256 + threadIdx.x;
    if (row >= NROWS) return;
    const float nu2 = g_nu2[row], dub = g_dub[row], nb2 = g_nb2;

    float t     = sqrtf(nu2);
    float r     = fmaxf(t, EPSF);
    float scale = fminf(20.f / r, 1.f);
    float ru    = scale * t;
    float coefe = sinhf(ru) / fmaxf(ru, EPSF);
    float cy    = coefe * scale;
    float ny2   = cy * cy * nu2;
    float dyb   = cy * dub;
    float bx    = 1.f / fmaxf(sqrtf(1.f + ny2), TINYF);
    float kk    = bx / (1.f + bx);
    float dxv   = dyb * (1.f + kk * ny2);
    float nbt2  = nb2 + 2.f * kk * dyb * dyb + kk * kk * dyb * dyb * ny2;
    float gpvv  = fmaxf(nbt2 - dxv * dxv / (1.f + ny2), TINYF);
    float rg    = sqrtf(gpvv);
    float opb   = 1.f + bx;
    float mopb  = fmaxf(opb, TINYF);
    float c2    = -(bx * bx * bx) / (mopb * mopb);
    float lam   = opb / fmaxf(bx, TINYF);
    float z     = fminf(rg, 20.f);
    float sc    = (fabsf(z) < EPSF) ? (1.f + z * z / 6.f)
                                    : (sinhf(z) / fmaxf(z, EPSF));
    float L     = lam * sc;
    float wb    = L * kk;
    float wy    = L * (kk * kk * dyb + c2 * dxv);
    float nw2   = wb * wb * nb2 + 2.f * wb * wy * dyb + wy * wy * ny2;
    float dyw   = wb * dyb + wy * ny2;
    float bw    = 1.f / fmaxf(sqrtf(1.f + nw2), TINYF);
    float coefg = kk * dyw + (1.f - bw) / bw;
    g_alpha[row] = (1.f + coefg + wy) * cy;
    g_gamma[row] = wb;
}

// ---------------- Kernel 4: streaming epilogue (fp16 in, fp32 out) ----------------
__global__ void epilogue_kernel(float* __restrict__ out, const float* __restrict__ b) {
    int row = blockIdx.x;
    const float alpha = g_alpha[row], gamma = g_gamma[row];
    const __half* uh = g_Uh + (size_t)row * MDIM;
    float* orow = out + (size_t)row * MDIM;
    int j = threadIdx.x;             // 256 threads x 8 elems = 2048 cols
    // load 8 fp16 u values (16B)
    uint4 raw = *(const uint4*)(uh + j * 8);
    __half2 h01 = *(__half2*)&raw.x, h23 = *(__half2*)&raw.y;
    __half2 h45 = *(__half2*)&raw.z, h67 = *(__half2*)&raw.w;
    float2 u01 = __half22float2(h01), u23 = __half22float2(h23);
    float2 u45 = __half22float2(h45), u67 = __half22float2(h67);
    const float4* b4 = (const float4*)b;
    float4 bv0 = b4[2 * j], bv1 = b4[2 * j + 1];
    float4 o0, o1;
    o0.x = alpha * u01.x + gamma * bv0.x;
    o0.y = alpha * u01.y + gamma * bv0.y;
    o0.z = alpha * u23.x + gamma * bv0.z;
    o0.w = alpha * u23.y + gamma * bv0.w;
    o1.x = alpha * u45.x + gamma * bv1.x;
    o1.y = alpha * u45.y + gamma * bv1.y;
    o1.z = alpha * u67.x + gamma * bv1.z;
    o1.w = alpha * u67.y + gamma * bv1.w;
    float4* od = (float4*)(orow + j * 8);
    od[0] = o0;
    od[1] = o1;
}

// ---------------- Launch ----------------
extern "C" void kernel_launch(void* const* d_in, const int* in_sizes, int n_in,
                              void* d_out, int out_size) {
    const float* x = (const float*)d_in[0];   // [16384, 2048]
    const float* W = (const float*)d_in[1];   // [2048, 2048]
    const float* b = (const float*)d_in[2];   // [2048]
    float* out = (float*)d_out;               // [16384, 2048]

    cudaFuncSetAttribute(gemm_kernel, cudaFuncAttributeMaxDynamicSharedMemorySize, SMEM_DYN);

    prep_kernel<<<MDIM + NROWS, 256>>>(x, W, b);

    dim3 grid(MDIM / BN, NROWS / BM);      // (16, 128), 2048 CTAs, 2/SM
    gemm_kernel<<<grid, NTHREADS, SMEM_DYN>>>(b);

    coef_kernel<<<NROWS / 256, 256>>>();
    epilogue_kernel<<<NROWS, 256>>>(out, b);
}